// round 1
// baseline (speedup 1.0000x reference)
#include <cuda_runtime.h>
#include <cuda_bf16.h>
#include <cstdint>

// Problem constants
#define NB     4
#define HH     64
#define WW     64
#define EMBED  128
#define NH     4
#define HD     32
#define CTX    256
#define RANK   8
#define KER    7
#define K2     49
#define PAD    3
#define SCALE  0.17677669529663689f   // 32^-0.5
#define TOK    4096                   // tokens per batch (64*64)
#define NTOK   16384                  // total tokens

// ---------------- device scratch (static allocation: allowed) ----------------
__device__ float g_c2[NB * RANK];                 // alpha_b * c_proj[b][r]
__device__ float g_Weff[NB * 3 * EMBED * EMBED];  // [b][o][i]
__device__ float g_qkv[3 * NB * NH * TOK * HD];   // [s][b][h][tok][d]
__device__ float g_attn[NTOK * EMBED];            // [tok][h*32+d]

// ---------------- kernel 0: c2 = alpha * (context @ Blora) -------------------
__global__ void prep_kernel(const float* __restrict__ ctx,
                            const float* __restrict__ Blora,
                            const float* __restrict__ g1w,
                            const float* __restrict__ g1b,
                            const float* __restrict__ g2w,
                            const float* __restrict__ g2b) {
    __shared__ float scp[32];
    __shared__ float sh[64];
    __shared__ float sal[4];
    int t = threadIdx.x;
    if (t < 32) {
        int b = t >> 3, r = t & 7;
        float s = 0.f;
        #pragma unroll 4
        for (int c = 0; c < CTX; ++c)
            s = fmaf(ctx[b * CTX + c], Blora[c * RANK + r], s);
        scp[t] = s;
    } else if (t >= 64) {
        int u = t - 64;
        int b = u >> 4, j = u & 15;
        float hj = g1b[j];
        #pragma unroll 4
        for (int c = 0; c < CTX; ++c)
            hj = fmaf(ctx[b * CTX + c], g1w[j * CTX + c], hj);
        sh[u] = fmaxf(hj, 0.f) * g2w[j];
    }
    __syncthreads();
    if (t < 4) {
        float s = g2b[0];
        #pragma unroll
        for (int j = 0; j < 16; ++j) s += sh[t * 16 + j];
        sal[t] = 1.f / (1.f + __expf(-s));
    }
    __syncthreads();
    if (t < 32) g_c2[t] = sal[t >> 3] * scp[t];
}

// ---------------- kernel 1: W_eff = Wqkv + Vlora diag(c2) A^T ----------------
__global__ void weff_kernel(const float* __restrict__ Wqkv,
                            const float* __restrict__ A,
                            const float* __restrict__ Vl) {
    int idx = blockIdx.x * 256 + threadIdx.x;     // 4*384*128 = 196608 total
    int b = idx / (3 * EMBED * EMBED);
    int rem = idx - b * (3 * EMBED * EMBED);
    int o = rem >> 7, i = rem & 127;
    float w = Wqkv[rem];
    const float* c2 = g_c2 + b * RANK;
    #pragma unroll
    for (int r = 0; r < RANK; ++r)
        w = fmaf(Vl[o * RANK + r] * c2[r], A[i * RANK + r], w);
    g_Weff[idx] = w;
}

// ---------------- GEMM: 128x128 tile, BK=8, 8x8 per-thread -------------------
// C[t][o] = sum_k Ab[t][k] * Wb[o][k]
template <bool QKV>
__global__ __launch_bounds__(256, 2)
void gemm_kernel(const float* __restrict__ Aglob,
                 const float* __restrict__ Wglob,
                 const float* __restrict__ bias,
                 float* __restrict__ outp) {
    __shared__ float sA[8][128];
    __shared__ float sB[8][128];
    const int tid = threadIdx.x;
    const int b = blockIdx.z;
    const int m0 = blockIdx.x * 128;
    const int n0 = blockIdx.y * 128;

    const float* Ab;
    const float* Wb;
    if (QKV) {
        Ab = Aglob + (size_t)b * TOK * EMBED;
        Wb = g_Weff + (size_t)b * 3 * EMBED * EMBED;
    } else {
        Ab = g_attn;
        Wb = Wglob;
    }

    const int arow = tid >> 1;
    const int ac4 = (tid & 1) * 4;
    const float* aptr = Ab + (size_t)(m0 + arow) * EMBED + ac4;
    const float* bptr = Wb + (size_t)(n0 + arow) * EMBED + ac4;

    float4 pa = *(const float4*)aptr;
    float4 pb = *(const float4*)bptr;

    float acc[8][8];
    #pragma unroll
    for (int i = 0; i < 8; ++i)
        #pragma unroll
        for (int j = 0; j < 8; ++j) acc[i][j] = 0.f;

    const int ty = tid >> 4;   // 0..15 -> m
    const int tx = tid & 15;   // 0..15 -> n

    #pragma unroll 1
    for (int kt = 0; kt < 16; ++kt) {
        sA[ac4 + 0][arow] = pa.x; sA[ac4 + 1][arow] = pa.y;
        sA[ac4 + 2][arow] = pa.z; sA[ac4 + 3][arow] = pa.w;
        sB[ac4 + 0][arow] = pb.x; sB[ac4 + 1][arow] = pb.y;
        sB[ac4 + 2][arow] = pb.z; sB[ac4 + 3][arow] = pb.w;
        __syncthreads();
        if (kt < 15) {
            pa = *(const float4*)(aptr + (kt + 1) * 8);
            pb = *(const float4*)(bptr + (kt + 1) * 8);
        }
        #pragma unroll
        for (int kk = 0; kk < 8; ++kk) {
            float a[8], bb[8];
            *(float4*)&a[0]  = *(const float4*)&sA[kk][ty * 8];
            *(float4*)&a[4]  = *(const float4*)&sA[kk][ty * 8 + 4];
            *(float4*)&bb[0] = *(const float4*)&sB[kk][tx * 8];
            *(float4*)&bb[4] = *(const float4*)&sB[kk][tx * 8 + 4];
            #pragma unroll
            for (int i = 0; i < 8; ++i)
                #pragma unroll
                for (int j = 0; j < 8; ++j)
                    acc[i][j] = fmaf(a[i], bb[j], acc[i][j]);
        }
        __syncthreads();
    }

    // epilogue
    const int o0 = n0 + tx * 8;
    float4 bias0 = *(const float4*)&bias[o0];
    float4 bias1 = *(const float4*)&bias[o0 + 4];

    if (QKV) {
        // o -> (s, h, d); tx*8 aligned so all 8 cols share s and h
        const int s = o0 >> 7;
        const int h = (o0 >> 5) & 3;
        const int d0 = o0 & 31;
        float* basep = g_qkv + ((size_t)(s * 16 + b * 4 + h) * TOK) * HD + d0;
        #pragma unroll
        for (int i = 0; i < 8; ++i) {
            int t = m0 + ty * 8 + i;
            float4 r0 = make_float4(acc[i][0] + bias0.x, acc[i][1] + bias0.y,
                                    acc[i][2] + bias0.z, acc[i][3] + bias0.w);
            float4 r1 = make_float4(acc[i][4] + bias1.x, acc[i][5] + bias1.y,
                                    acc[i][6] + bias1.z, acc[i][7] + bias1.w);
            *(float4*)(basep + (size_t)t * HD)     = r0;
            *(float4*)(basep + (size_t)t * HD + 4) = r1;
        }
    } else {
        #pragma unroll
        for (int i = 0; i < 8; ++i) {
            int t = m0 + ty * 8 + i;
            float4 r0 = make_float4(acc[i][0] + bias0.x, acc[i][1] + bias0.y,
                                    acc[i][2] + bias0.z, acc[i][3] + bias0.w);
            float4 r1 = make_float4(acc[i][4] + bias1.x, acc[i][5] + bias1.y,
                                    acc[i][6] + bias1.z, acc[i][7] + bias1.w);
            *(float4*)(outp + (size_t)t * EMBED + o0)     = r0;
            *(float4*)(outp + (size_t)t * EMBED + o0 + 4) = r1;
        }
    }
}

// ---------------- kernel 3: neighborhood attention ---------------------------
// tile: 8 rows (i) x 16 cols (j), 128 threads, 1 token each.
// halo: 14 x 22 x 32 floats for k and v in dynamic smem (zero-filled = padding).
#define TILE_I 8
#define TILE_J 16
#define HALO_I 14
#define HALO_J 22
#define HALO_F (HALO_I * HALO_J * HD)       // 9856 floats per tensor
#define ATTN_SMEM (2 * HALO_F * 4)          // 78848 bytes

__global__ void attn_kernel() {
    extern __shared__ float smem[];
    float* sk = smem;
    float* sv = smem + HALO_F;

    const int tid = threadIdx.x;
    const int z = blockIdx.z;             // b*4 + h
    const int b = z >> 2, h = z & 3;
    const int j0 = blockIdx.x * TILE_J;
    const int i0 = blockIdx.y * TILE_I;

    const int bh = b * 4 + h;
    const float* kg = g_qkv + (size_t)(16 + bh) * TOK * HD;   // s=1
    const float* vg = g_qkv + (size_t)(32 + bh) * TOK * HD;   // s=2
    const float* qg = g_qkv + (size_t)bh * TOK * HD;          // s=0

    // cooperative halo load (zero OOB), fully contiguous float4s
    const int nf4 = HALO_I * HALO_J * (HD / 4);   // 2464
    for (int idx = tid; idx < nf4; idx += 128) {
        int r   = idx / (HALO_J * 8);
        int rem = idx - r * (HALO_J * 8);
        int c   = rem >> 3;
        int f   = rem & 7;
        int gi = i0 - PAD + r;
        int gj = j0 - PAD + c;
        float4 kv = make_float4(0.f, 0.f, 0.f, 0.f);
        float4 vv = kv;
        if (gi >= 0 && gi < HH && gj >= 0 && gj < WW) {
            size_t go = ((size_t)(gi * WW + gj)) * HD + f * 4;
            kv = *(const float4*)(kg + go);
            vv = *(const float4*)(vg + go);
        }
        ((float4*)sk)[idx] = kv;
        ((float4*)sv)[idx] = vv;
    }
    __syncthreads();

    const int li = tid >> 4;     // 0..7
    const int lj = tid & 15;     // 0..15
    const int gi = i0 + li, gj = j0 + lj;

    float4 rq[8];
    {
        const float4* qp = (const float4*)(qg + ((size_t)(gi * WW + gj)) * HD);
        #pragma unroll
        for (int q = 0; q < 8; ++q) rq[q] = qp[q];
    }

    float4 acc[8];
    #pragma unroll
    for (int q = 0; q < 8; ++q) acc[q] = make_float4(0.f, 0.f, 0.f, 0.f);
    float den = 0.f;

    // logits are tiny (|.|<~0.5): single-pass online softmax without max-sub
    #pragma unroll 1
    for (int di = 0; di < KER; ++di) {
        #pragma unroll 1
        for (int dj = 0; dj < KER; ++dj) {
            const int hidx = ((li + di) * HALO_J + (lj + dj)) * HD;
            const float4* k4 = (const float4*)(sk + hidx);
            float d0 = 0.f, d1 = 0.f, d2 = 0.f, d3 = 0.f;
            #pragma unroll
            for (int q = 0; q < 8; ++q) {
                float4 kv = k4[q];
                d0 = fmaf(rq[q].x, kv.x, d0);
                d1 = fmaf(rq[q].y, kv.y, d1);
                d2 = fmaf(rq[q].z, kv.z, d2);
                d3 = fmaf(rq[q].w, kv.w, d3);
            }
            float p = __expf(((d0 + d1) + (d2 + d3)) * SCALE);
            den += p;
            const float4* v4 = (const float4*)(sv + hidx);
            #pragma unroll
            for (int q = 0; q < 8; ++q) {
                float4 vv = v4[q];
                acc[q].x = fmaf(p, vv.x, acc[q].x);
                acc[q].y = fmaf(p, vv.y, acc[q].y);
                acc[q].z = fmaf(p, vv.z, acc[q].z);
                acc[q].w = fmaf(p, vv.w, acc[q].w);
            }
        }
    }

    const float inv = 1.f / den;
    float* op = g_attn + ((size_t)(b * TOK + gi * WW + gj)) * EMBED + h * HD;
    #pragma unroll
    for (int q = 0; q < 8; ++q) {
        float4 r = make_float4(acc[q].x * inv, acc[q].y * inv,
                               acc[q].z * inv, acc[q].w * inv);
        *(float4*)(op + q * 4) = r;
    }
}

// ---------------- launch -----------------------------------------------------
extern "C" void kernel_launch(void* const* d_in, const int* in_sizes, int n_in,
                              void* d_out, int out_size) {
    const float* x     = (const float*)d_in[0];
    const float* ctx   = (const float*)d_in[1];
    const float* Wqkv  = (const float*)d_in[2];
    const float* bqkv  = (const float*)d_in[3];
    const float* A     = (const float*)d_in[4];
    const float* Blora = (const float*)d_in[5];
    const float* Vlora = (const float*)d_in[6];
    const float* g1w   = (const float*)d_in[7];
    const float* g1b   = (const float*)d_in[8];
    const float* g2w   = (const float*)d_in[9];
    const float* g2b   = (const float*)d_in[10];
    const float* Wproj = (const float*)d_in[11];
    const float* bproj = (const float*)d_in[12];
    float* out = (float*)d_out;

    cudaFuncSetAttribute(attn_kernel,
                         cudaFuncAttributeMaxDynamicSharedMemorySize, ATTN_SMEM);

    prep_kernel<<<1, 128>>>(ctx, Blora, g1w, g1b, g2w, g2b);
    weff_kernel<<<768, 256>>>(Wqkv, A, Vlora);
    gemm_kernel<true><<<dim3(32, 3, 4), 256>>>(x, nullptr, bqkv, nullptr);
    attn_kernel<<<dim3(WW / TILE_J, HH / TILE_I, NB * NH), 128, ATTN_SMEM>>>();
    gemm_kernel<false><<<dim3(128, 1, 1), 256>>>(nullptr, Wproj, bproj, out);
}

// round 2
// speedup vs baseline: 2.3659x; 2.3659x over previous
#include <cuda_runtime.h>
#include <cuda_bf16.h>
#include <cstdint>

// Problem constants
#define NB     4
#define HH     64
#define WW     64
#define EMBED  128
#define NH     4
#define HD     32
#define CTX    256
#define RANK   8
#define KER    7
#define K2     49
#define PAD    3
#define SCALE  0.17677669529663689f   // 32^-0.5
#define TOK    4096                   // tokens per batch (64*64)
#define NTOK   16384                  // total tokens

// ---------------- device scratch (static allocation: allowed) ----------------
__device__ float g_c2[NB * RANK];                 // alpha_b * c_proj[b][r]
__device__ float g_Weff[NB * 3 * EMBED * EMBED];  // [b][o][i]
__device__ float g_qkv[3 * NB * NH * TOK * HD];   // [s][b][h][tok][d]
__device__ float g_attn[NTOK * EMBED];            // [tok][h*32+d]

// ---------------- kernel 0: c2 = alpha * (context @ Blora) -------------------
__global__ void prep_kernel(const float* __restrict__ ctx,
                            const float* __restrict__ Blora,
                            const float* __restrict__ g1w,
                            const float* __restrict__ g1b,
                            const float* __restrict__ g2w,
                            const float* __restrict__ g2b) {
    __shared__ float scp[32];
    __shared__ float sh[64];
    __shared__ float sal[4];
    int t = threadIdx.x;
    if (t < 32) {
        int b = t >> 3, r = t & 7;
        float s = 0.f;
        #pragma unroll 4
        for (int c = 0; c < CTX; ++c)
            s = fmaf(ctx[b * CTX + c], Blora[c * RANK + r], s);
        scp[t] = s;
    } else if (t >= 64) {
        int u = t - 64;
        int b = u >> 4, j = u & 15;
        float hj = g1b[j];
        #pragma unroll 4
        for (int c = 0; c < CTX; ++c)
            hj = fmaf(ctx[b * CTX + c], g1w[j * CTX + c], hj);
        sh[u] = fmaxf(hj, 0.f) * g2w[j];
    }
    __syncthreads();
    if (t < 4) {
        float s = g2b[0];
        #pragma unroll
        for (int j = 0; j < 16; ++j) s += sh[t * 16 + j];
        sal[t] = 1.f / (1.f + __expf(-s));
    }
    __syncthreads();
    if (t < 32) g_c2[t] = sal[t >> 3] * scp[t];
}

// ---------------- kernel 1: W_eff = Wqkv + Vlora diag(c2) A^T ----------------
__global__ void weff_kernel(const float* __restrict__ Wqkv,
                            const float* __restrict__ A,
                            const float* __restrict__ Vl) {
    int idx = blockIdx.x * 256 + threadIdx.x;     // 4*384*128 = 196608 total
    int b = idx / (3 * EMBED * EMBED);
    int rem = idx - b * (3 * EMBED * EMBED);
    int o = rem >> 7, i = rem & 127;
    float w = Wqkv[rem];
    const float* c2 = g_c2 + b * RANK;
    #pragma unroll
    for (int r = 0; r < RANK; ++r)
        w = fmaf(Vl[o * RANK + r] * c2[r], A[i * RANK + r], w);
    g_Weff[idx] = w;
}

// ---------------- GEMM: 128x128 tile, BK=8, 8x8 per-thread -------------------
// C[t][o] = sum_k Ab[t][k] * Wb[o][k]
template <bool QKV>
__global__ __launch_bounds__(256, 2)
void gemm_kernel(const float* __restrict__ Aglob,
                 const float* __restrict__ Wglob,
                 const float* __restrict__ bias,
                 float* __restrict__ outp) {
    __shared__ float sA[8][128];
    __shared__ float sB[8][128];
    const int tid = threadIdx.x;
    const int b = blockIdx.z;
    const int m0 = blockIdx.x * 128;
    const int n0 = blockIdx.y * 128;

    const float* Ab;
    const float* Wb;
    if (QKV) {
        Ab = Aglob + (size_t)b * TOK * EMBED;
        Wb = g_Weff + (size_t)b * 3 * EMBED * EMBED;
    } else {
        Ab = g_attn;
        Wb = Wglob;
    }

    const int arow = tid >> 1;
    const int ac4 = (tid & 1) * 4;
    const float* aptr = Ab + (size_t)(m0 + arow) * EMBED + ac4;
    const float* bptr = Wb + (size_t)(n0 + arow) * EMBED + ac4;

    float4 pa = *(const float4*)aptr;
    float4 pb = *(const float4*)bptr;

    float acc[8][8];
    #pragma unroll
    for (int i = 0; i < 8; ++i)
        #pragma unroll
        for (int j = 0; j < 8; ++j) acc[i][j] = 0.f;

    const int ty = tid >> 4;   // 0..15 -> m
    const int tx = tid & 15;   // 0..15 -> n

    #pragma unroll 1
    for (int kt = 0; kt < 16; ++kt) {
        sA[ac4 + 0][arow] = pa.x; sA[ac4 + 1][arow] = pa.y;
        sA[ac4 + 2][arow] = pa.z; sA[ac4 + 3][arow] = pa.w;
        sB[ac4 + 0][arow] = pb.x; sB[ac4 + 1][arow] = pb.y;
        sB[ac4 + 2][arow] = pb.z; sB[ac4 + 3][arow] = pb.w;
        __syncthreads();
        if (kt < 15) {
            pa = *(const float4*)(aptr + (kt + 1) * 8);
            pb = *(const float4*)(bptr + (kt + 1) * 8);
        }
        #pragma unroll
        for (int kk = 0; kk < 8; ++kk) {
            float a[8], bb[8];
            *(float4*)&a[0]  = *(const float4*)&sA[kk][ty * 8];
            *(float4*)&a[4]  = *(const float4*)&sA[kk][ty * 8 + 4];
            *(float4*)&bb[0] = *(const float4*)&sB[kk][tx * 8];
            *(float4*)&bb[4] = *(const float4*)&sB[kk][tx * 8 + 4];
            #pragma unroll
            for (int i = 0; i < 8; ++i)
                #pragma unroll
                for (int j = 0; j < 8; ++j)
                    acc[i][j] = fmaf(a[i], bb[j], acc[i][j]);
        }
        __syncthreads();
    }

    // epilogue
    const int o0 = n0 + tx * 8;
    float4 bias0 = *(const float4*)&bias[o0];
    float4 bias1 = *(const float4*)&bias[o0 + 4];

    if (QKV) {
        // o -> (s, h, d); tx*8 aligned so all 8 cols share s and h
        const int s = o0 >> 7;
        const int h = (o0 >> 5) & 3;
        const int d0 = o0 & 31;
        float* basep = g_qkv + ((size_t)(s * 16 + b * 4 + h) * TOK) * HD + d0;
        #pragma unroll
        for (int i = 0; i < 8; ++i) {
            int t = m0 + ty * 8 + i;
            float4 r0 = make_float4(acc[i][0] + bias0.x, acc[i][1] + bias0.y,
                                    acc[i][2] + bias0.z, acc[i][3] + bias0.w);
            float4 r1 = make_float4(acc[i][4] + bias1.x, acc[i][5] + bias1.y,
                                    acc[i][6] + bias1.z, acc[i][7] + bias1.w);
            *(float4*)(basep + (size_t)t * HD)     = r0;
            *(float4*)(basep + (size_t)t * HD + 4) = r1;
        }
    } else {
        #pragma unroll
        for (int i = 0; i < 8; ++i) {
            int t = m0 + ty * 8 + i;
            float4 r0 = make_float4(acc[i][0] + bias0.x, acc[i][1] + bias0.y,
                                    acc[i][2] + bias0.z, acc[i][3] + bias0.w);
            float4 r1 = make_float4(acc[i][4] + bias1.x, acc[i][5] + bias1.y,
                                    acc[i][6] + bias1.z, acc[i][7] + bias1.w);
            *(float4*)(outp + (size_t)t * EMBED + o0)     = r0;
            *(float4*)(outp + (size_t)t * EMBED + o0 + 4) = r1;
        }
    }
}

// ---------------- kernel 3: neighborhood attention ---------------------------
// tile: 8 rows (i) x 16 cols (j), 128 threads, 1 token each.
// halo: 14 x 22 positions. Smem layout is PLANAR + padded for zero bank
// conflicts: 8 planes (one per float4 chunk of head_dim), each plane holds
// one float4 per halo position. Plane stride 1252 floats (== 4 mod 32) so
// writer lanes (8 consecutive lanes -> 8 planes, same position) hit distinct
// bank groups, and reader lanes (consecutive positions, same plane) are
// contiguous 16B -> conflict-free LDS.128/STS.128.
// Two passes (K then V) reuse ONE 40KB buffer; softmax weights p[49] live in
// registers between passes.
#define TILE_I 8
#define TILE_J 16
#define HALO_I 14
#define HALO_J 22
#define NPOS   (HALO_I * HALO_J)        // 308 positions
#define NF4    (NPOS * 8)               // 2464 float4 per tensor
#define PLANE  1252                     // floats per plane (308*4=1232, pad to ==4 mod 32)
#define ATTN_SMEM (8 * PLANE * 4)       // 40064 bytes

__global__ __launch_bounds__(128, 4) void attn_kernel() {
    extern __shared__ float smem[];

    const int tid = threadIdx.x;
    const int z = blockIdx.z;             // b*4 + h
    const int b = z >> 2, h = z & 3;
    const int j0 = blockIdx.x * TILE_J;
    const int i0 = blockIdx.y * TILE_I;

    const int bh = b * 4 + h;
    const float* qg = g_qkv + (size_t)bh * TOK * HD;          // s=0
    const float* kg = g_qkv + (size_t)(16 + bh) * TOK * HD;   // s=1
    const float* vg = g_qkv + (size_t)(32 + bh) * TOK * HD;   // s=2

    const int li = tid >> 4;     // 0..7
    const int lj = tid & 15;     // 0..15
    const int gi = i0 + li, gj = j0 + lj;

    // ---- load K halo (planar, zero OOB = matches reference zero-padding) ----
    #pragma unroll 1
    for (int idx = tid; idx < NF4; idx += 128) {
        int pos = idx >> 3, f = idx & 7;
        int r = pos / HALO_J, c = pos - r * HALO_J;
        int ri = i0 - PAD + r, rj = j0 - PAD + c;
        float4 kv = make_float4(0.f, 0.f, 0.f, 0.f);
        if (ri >= 0 && ri < HH && rj >= 0 && rj < WW)
            kv = *(const float4*)(kg + ((size_t)(ri * WW + rj)) * HD + f * 4);
        *(float4*)(smem + f * PLANE + pos * 4) = kv;
    }

    // q registers with SCALE pre-folded
    float4 rq[8];
    {
        const float4* qp = (const float4*)(qg + ((size_t)(gi * WW + gj)) * HD);
        #pragma unroll
        for (int q = 0; q < 8; ++q) {
            float4 v = qp[q];
            rq[q] = make_float4(v.x * SCALE, v.y * SCALE, v.z * SCALE, v.w * SCALE);
        }
    }
    __syncthreads();

    // ---- pass 1: logits -> p[49] in registers ----
    float p[K2];
    float den = 0.f;
    #pragma unroll
    for (int di = 0; di < KER; ++di) {
        #pragma unroll
        for (int dj = 0; dj < KER; ++dj) {
            const int pos4 = ((li + di) * HALO_J + (lj + dj)) * 4;
            float d0 = 0.f, d1 = 0.f, d2 = 0.f, d3 = 0.f;
            #pragma unroll
            for (int q = 0; q < 8; ++q) {
                float4 kv = *(const float4*)(smem + q * PLANE + pos4);
                d0 = fmaf(rq[q].x, kv.x, d0);
                d1 = fmaf(rq[q].y, kv.y, d1);
                d2 = fmaf(rq[q].z, kv.z, d2);
                d3 = fmaf(rq[q].w, kv.w, d3);
            }
            float e = __expf((d0 + d1) + (d2 + d3));
            p[di * KER + dj] = e;
            den += e;
        }
    }
    __syncthreads();   // everyone done reading K before overwrite

    // ---- load V halo into the same buffer ----
    #pragma unroll 1
    for (int idx = tid; idx < NF4; idx += 128) {
        int pos = idx >> 3, f = idx & 7;
        int r = pos / HALO_J, c = pos - r * HALO_J;
        int ri = i0 - PAD + r, rj = j0 - PAD + c;
        float4 vv = make_float4(0.f, 0.f, 0.f, 0.f);
        if (ri >= 0 && ri < HH && rj >= 0 && rj < WW)
            vv = *(const float4*)(vg + ((size_t)(ri * WW + rj)) * HD + f * 4);
        *(float4*)(smem + f * PLANE + pos * 4) = vv;
    }
    __syncthreads();

    // ---- pass 2: out = sum p * v ----
    float4 acc[8];
    #pragma unroll
    for (int q = 0; q < 8; ++q) acc[q] = make_float4(0.f, 0.f, 0.f, 0.f);

    #pragma unroll
    for (int di = 0; di < KER; ++di) {
        #pragma unroll
        for (int dj = 0; dj < KER; ++dj) {
            const int pos4 = ((li + di) * HALO_J + (lj + dj)) * 4;
            const float pw = p[di * KER + dj];
            #pragma unroll
            for (int q = 0; q < 8; ++q) {
                float4 vv = *(const float4*)(smem + q * PLANE + pos4);
                acc[q].x = fmaf(pw, vv.x, acc[q].x);
                acc[q].y = fmaf(pw, vv.y, acc[q].y);
                acc[q].z = fmaf(pw, vv.z, acc[q].z);
                acc[q].w = fmaf(pw, vv.w, acc[q].w);
            }
        }
    }

    const float inv = 1.f / den;
    float* op = g_attn + ((size_t)(b * TOK + gi * WW + gj)) * EMBED + h * HD;
    #pragma unroll
    for (int q = 0; q < 8; ++q) {
        float4 r = make_float4(acc[q].x * inv, acc[q].y * inv,
                               acc[q].z * inv, acc[q].w * inv);
        *(float4*)(op + q * 4) = r;
    }
}

// ---------------- launch -----------------------------------------------------
extern "C" void kernel_launch(void* const* d_in, const int* in_sizes, int n_in,
                              void* d_out, int out_size) {
    const float* x     = (const float*)d_in[0];
    const float* ctx   = (const float*)d_in[1];
    const float* Wqkv  = (const float*)d_in[2];
    const float* bqkv  = (const float*)d_in[3];
    const float* A     = (const float*)d_in[4];
    const float* Blora = (const float*)d_in[5];
    const float* Vlora = (const float*)d_in[6];
    const float* g1w   = (const float*)d_in[7];
    const float* g1b   = (const float*)d_in[8];
    const float* g2w   = (const float*)d_in[9];
    const float* g2b   = (const float*)d_in[10];
    const float* Wproj = (const float*)d_in[11];
    const float* bproj = (const float*)d_in[12];
    float* out = (float*)d_out;

    cudaFuncSetAttribute(attn_kernel,
                         cudaFuncAttributeMaxDynamicSharedMemorySize, ATTN_SMEM);

    prep_kernel<<<1, 128>>>(ctx, Blora, g1w, g1b, g2w, g2b);
    weff_kernel<<<768, 256>>>(Wqkv, A, Vlora);
    gemm_kernel<true><<<dim3(32, 3, 4), 256>>>(x, nullptr, bqkv, nullptr);
    attn_kernel<<<dim3(WW / TILE_J, HH / TILE_I, NB * NH), 128, ATTN_SMEM>>>();
    gemm_kernel<false><<<dim3(128, 1, 1), 256>>>(nullptr, Wproj, bproj, out);
}

// round 4
// speedup vs baseline: 3.2726x; 1.3832x over previous
#include <cuda_runtime.h>
#include <cuda_bf16.h>
#include <cstdint>

// Problem constants
#define NB     4
#define HH     64
#define WW     64
#define EMBED  128
#define NH     4
#define HD     32
#define CTX    256
#define RANK   8
#define KER    7
#define K2     49
#define PAD    3
#define SCALE  0.17677669529663689f   // 32^-0.5
#define TOK    4096                   // tokens per batch (64*64)
#define NTOK   16384                  // total tokens

// ---------------- device scratch (static allocation: allowed) ----------------
__device__ float g_c2[NB * RANK];                 // alpha_b * c_proj[b][r]
__device__ float g_Weff[NB * 3 * EMBED * EMBED];  // [b][o][i]
__device__ float g_qkv[3 * NB * NH * TOK * HD];   // [s][b][h][tok][d]
__device__ float g_attn[NTOK * EMBED];            // [tok][h*32+d]

// ---------------- kernel 0: c2 = alpha * (context @ Blora) -------------------
__global__ void prep_kernel(const float* __restrict__ ctx,
                            const float* __restrict__ Blora,
                            const float* __restrict__ g1w,
                            const float* __restrict__ g1b,
                            const float* __restrict__ g2w,
                            const float* __restrict__ g2b) {
    __shared__ float scp[32];
    __shared__ float sh[64];
    __shared__ float sal[4];
    int t = threadIdx.x;
    if (t < 32) {
        int b = t >> 3, r = t & 7;
        float s = 0.f;
        #pragma unroll 4
        for (int c = 0; c < CTX; ++c)
            s = fmaf(ctx[b * CTX + c], Blora[c * RANK + r], s);
        scp[t] = s;
    } else if (t >= 64) {
        int u = t - 64;
        int b = u >> 4, j = u & 15;
        float hj = g1b[j];
        #pragma unroll 4
        for (int c = 0; c < CTX; ++c)
            hj = fmaf(ctx[b * CTX + c], g1w[j * CTX + c], hj);
        sh[u] = fmaxf(hj, 0.f) * g2w[j];
    }
    __syncthreads();
    if (t < 4) {
        float s = g2b[0];
        #pragma unroll
        for (int j = 0; j < 16; ++j) s += sh[t * 16 + j];
        sal[t] = 1.f / (1.f + __expf(-s));
    }
    __syncthreads();
    if (t < 32) g_c2[t] = sal[t >> 3] * scp[t];
}

// ---------------- kernel 1: W_eff = Wqkv + Vlora diag(c2) A^T ----------------
__global__ void weff_kernel(const float* __restrict__ Wqkv,
                            const float* __restrict__ A,
                            const float* __restrict__ Vl) {
    int idx = blockIdx.x * 256 + threadIdx.x;     // 4*384*128 = 196608 total
    int b = idx / (3 * EMBED * EMBED);
    int rem = idx - b * (3 * EMBED * EMBED);
    int o = rem >> 7, i = rem & 127;
    float w = Wqkv[rem];
    const float* c2 = g_c2 + b * RANK;
    #pragma unroll
    for (int r = 0; r < RANK; ++r)
        w = fmaf(Vl[o * RANK + r] * c2[r], A[i * RANK + r], w);
    g_Weff[idx] = w;
}

// ================== bf16x3 tensor-core GEMM (mma.sync path) ==================
// C[m][n] = sum_k A[m][k] * B[n][k], fp32 in/out.
// Each fp32 operand is split a = a_hi + a_lo (bf16 each); D accumulates
// hh + hl + lh in fp32 -> error ~2^-18 per product.
// CTA tile 128(M) x 128(N) x 128(K whole). 8 warps in 4(m) x 2(n), each
// computing 32x64 via m16n8k16 mma. Smem rows padded to 272B: ldmatrix row
// addresses hit banks 4*lane -> conflict-free, no swizzle needed.
#define RSTRIDE 272
#define SM_AHI  0
#define SM_ALO  (128 * RSTRIDE)
#define SM_BHI  (2 * 128 * RSTRIDE)
#define SM_BLO  (3 * 128 * RSTRIDE)
#define GEMM_SMEM (4 * 128 * RSTRIDE)   // 139264 bytes

__device__ __forceinline__ uint32_t smem_u32(const void* p) {
    uint32_t a;
    asm("{ .reg .u64 t; cvta.to.shared.u64 t, %1; cvt.u32.u64 %0, t; }"
        : "=r"(a) : "l"(p));
    return a;
}

#define LDM4(r, addr) \
    asm volatile("ldmatrix.sync.aligned.m8n8.x4.shared.b16 {%0,%1,%2,%3}, [%4];" \
        : "=r"((r)[0]), "=r"((r)[1]), "=r"((r)[2]), "=r"((r)[3]) : "r"(addr))

#define MMA_BF16(c, a, b0, b1) \
    asm volatile("mma.sync.aligned.m16n8k16.row.col.f32.bf16.bf16.f32 " \
        "{%0,%1,%2,%3}, {%4,%5,%6,%7}, {%8,%9}, {%0,%1,%2,%3};" \
        : "+f"((c)[0]), "+f"((c)[1]), "+f"((c)[2]), "+f"((c)[3]) \
        : "r"((a)[0]), "r"((a)[1]), "r"((a)[2]), "r"((a)[3]), "r"(b0), "r"(b1))

// split one float into (hi, lo) bf16 and pack pairs into u32s
__device__ __forceinline__ void split2(float x, float y, uint32_t& hi, uint32_t& lo) {
    __nv_bfloat16 hx = __float2bfloat16_rn(x);
    __nv_bfloat16 hy = __float2bfloat16_rn(y);
    __nv_bfloat16 lx = __float2bfloat16_rn(x - __bfloat162float(hx));
    __nv_bfloat16 ly = __float2bfloat16_rn(y - __bfloat162float(hy));
    hi = ((uint32_t)__bfloat16_as_ushort(hy) << 16) | __bfloat16_as_ushort(hx);
    lo = ((uint32_t)__bfloat16_as_ushort(ly) << 16) | __bfloat16_as_ushort(lx);
}

template <bool QKV>
__global__ __launch_bounds__(256, 1)
void gemm_mma(const float* __restrict__ Aglob,
              const float* __restrict__ Wglob,
              const float* __restrict__ bias,
              float* __restrict__ outp) {
    extern __shared__ char smem[];
    const uint32_t sbase = smem_u32(smem);
    const int tid  = threadIdx.x;
    const int wid  = tid >> 5;
    const int lane = tid & 31;
    const int mw = wid >> 1;          // 0..3
    const int nw = wid & 1;           // 0..1
    const int b  = blockIdx.z;
    const int m0 = blockIdx.x * 128;
    const int n0 = blockIdx.y * 128;

    const float* srcA = QKV ? Aglob + ((size_t)b * TOK + m0) * EMBED
                            : g_attn + (size_t)m0 * EMBED;
    const float* srcB = QKV ? g_Weff + (size_t)b * 3 * EMBED * EMBED + (size_t)n0 * EMBED
                            : Wglob + (size_t)n0 * EMBED;

    // ---- fill A/B tiles: fp32 -> (hi, lo) bf16 planes, 272B row stride ----
    #pragma unroll
    for (int it = 0; it < 16; ++it) {
        int idx = it * 256 + tid;            // 4096 float4 slots
        int row = idx >> 5, c4 = idx & 31;
        float4 v = *(const float4*)(srcA + (size_t)row * EMBED + c4 * 4);
        uint32_t h0, l0, h1, l1;
        split2(v.x, v.y, h0, l0);
        split2(v.z, v.w, h1, l1);
        uint32_t off = row * RSTRIDE + c4 * 8;
        *(uint2*)(smem + SM_AHI + off) = make_uint2(h0, h1);
        *(uint2*)(smem + SM_ALO + off) = make_uint2(l0, l1);
    }
    #pragma unroll
    for (int it = 0; it < 16; ++it) {
        int idx = it * 256 + tid;
        int row = idx >> 5, c4 = idx & 31;
        float4 v = *(const float4*)(srcB + (size_t)row * EMBED + c4 * 4);
        uint32_t h0, l0, h1, l1;
        split2(v.x, v.y, h0, l0);
        split2(v.z, v.w, h1, l1);
        uint32_t off = row * RSTRIDE + c4 * 8;
        *(uint2*)(smem + SM_BHI + off) = make_uint2(h0, h1);
        *(uint2*)(smem + SM_BLO + off) = make_uint2(l0, l1);
    }
    __syncthreads();

    // ---- ldmatrix base addresses (lane-dependent, kt byte offset added later)
    // A x4: lanes 0-7: m0-7 k0 | 8-15: m8-15 k0 | 16-23: m0-7 k8 | 24-31: m8-15 k8
    const int arow = mw * 32 + (lane & 7) + ((lane >> 3) & 1) * 8;
    const uint32_t akb = ((lane >> 4) & 1) * 16;
    uint32_t aHi[2], aLo[2];
    #pragma unroll
    for (int mt = 0; mt < 2; ++mt) {
        uint32_t ro = (arow + mt * 16) * RSTRIDE + akb;
        aHi[mt] = sbase + SM_AHI + ro;
        aLo[mt] = sbase + SM_ALO + ro;
    }
    // B x4: lanes 0-7: n0-7 k0 | 8-15: n0-7 k8 | 16-23: n8-15 k0 | 24-31: n8-15 k8
    const int brow = nw * 64 + (lane & 7) + (lane >> 4) * 8;
    const uint32_t bkb = ((lane >> 3) & 1) * 16;
    uint32_t bHi[4], bLo[4];
    #pragma unroll
    for (int q = 0; q < 4; ++q) {
        uint32_t ro = (brow + q * 16) * RSTRIDE + bkb;
        bHi[q] = sbase + SM_BHI + ro;
        bLo[q] = sbase + SM_BLO + ro;
    }

    float acc[2][8][4];
    #pragma unroll
    for (int mt = 0; mt < 2; ++mt)
        #pragma unroll
        for (int nt = 0; nt < 8; ++nt)
            #pragma unroll
            for (int c = 0; c < 4; ++c) acc[mt][nt][c] = 0.f;

    // ---- main loop: 8 k-steps of 16 ----
    #pragma unroll
    for (int kt = 0; kt < 8; ++kt) {
        const uint32_t ko = kt * 32;
        uint32_t ah[2][4], al[2][4], bh[4][4], bl[4][4];
        #pragma unroll
        for (int mt = 0; mt < 2; ++mt) {
            LDM4(ah[mt], aHi[mt] + ko);
            LDM4(al[mt], aLo[mt] + ko);
        }
        #pragma unroll
        for (int q = 0; q < 4; ++q) {
            LDM4(bh[q], bHi[q] + ko);
            LDM4(bl[q], bLo[q] + ko);
        }
        #pragma unroll
        for (int mt = 0; mt < 2; ++mt)
            #pragma unroll
            for (int nt = 0; nt < 8; ++nt) {
                const int q = nt >> 1, r = (nt & 1) * 2;
                MMA_BF16(acc[mt][nt], ah[mt], bh[q][r], bh[q][r + 1]);
                MMA_BF16(acc[mt][nt], ah[mt], bl[q][r], bl[q][r + 1]);
                MMA_BF16(acc[mt][nt], al[mt], bh[q][r], bh[q][r + 1]);
            }
    }

    // ---- epilogue: c0,c1 -> (row, col..col+1); c2,c3 -> (row+8, ...) ----
    #pragma unroll
    for (int mt = 0; mt < 2; ++mt)
        #pragma unroll
        for (int nt = 0; nt < 8; ++nt) {
            const float* c = acc[mt][nt];
            const int col = n0 + nw * 64 + nt * 8 + (lane & 3) * 2;
            const int r0  = m0 + mw * 32 + mt * 16 + (lane >> 2);
            float2 bv = *(const float2*)(bias + col);
            float2 lo = make_float2(c[0] + bv.x, c[1] + bv.y);
            float2 hi = make_float2(c[2] + bv.x, c[3] + bv.y);
            if (QKV) {
                const int s = col >> 7, hh2 = (col >> 5) & 3, d = col & 31;
                float* p0 = g_qkv + ((size_t)(s * 16 + b * 4 + hh2) * TOK + r0) * HD + d;
                *(float2*)p0 = lo;
                *(float2*)(p0 + 8 * HD) = hi;
            } else {
                float* p0 = outp + (size_t)r0 * EMBED + col;
                *(float2*)p0 = lo;
                *(float2*)(p0 + 8 * EMBED) = hi;
            }
        }
}

// ---------------- kernel 3: neighborhood attention (unchanged R2) ------------
#define TILE_I 8
#define TILE_J 16
#define HALO_I 14
#define HALO_J 22
#define NPOS   (HALO_I * HALO_J)        // 308 positions
#define NF4    (NPOS * 8)               // 2464 float4 per tensor
#define PLANE  1252                     // floats per plane, ==4 mod 32
#define ATTN_SMEM (8 * PLANE * 4)       // 40064 bytes

__global__ __launch_bounds__(128, 4) void attn_kernel() {
    extern __shared__ float smemf[];

    const int tid = threadIdx.x;
    const int z = blockIdx.z;             // b*4 + h
    const int b = z >> 2, h = z & 3;
    const int j0 = blockIdx.x * TILE_J;
    const int i0 = blockIdx.y * TILE_I;

    const int bh = b * 4 + h;
    const float* qg = g_qkv + (size_t)bh * TOK * HD;          // s=0
    const float* kg = g_qkv + (size_t)(16 + bh) * TOK * HD;   // s=1
    const float* vg = g_qkv + (size_t)(32 + bh) * TOK * HD;   // s=2

    const int li = tid >> 4;     // 0..7
    const int lj = tid & 15;     // 0..15
    const int gi = i0 + li, gj = j0 + lj;

    #pragma unroll 1
    for (int idx = tid; idx < NF4; idx += 128) {
        int pos = idx >> 3, f = idx & 7;
        int r = pos / HALO_J, c = pos - r * HALO_J;
        int ri = i0 - PAD + r, rj = j0 - PAD + c;
        float4 kv = make_float4(0.f, 0.f, 0.f, 0.f);
        if (ri >= 0 && ri < HH && rj >= 0 && rj < WW)
            kv = *(const float4*)(kg + ((size_t)(ri * WW + rj)) * HD + f * 4);
        *(float4*)(smemf + f * PLANE + pos * 4) = kv;
    }

    float4 rq[8];
    {
        const float4* qp = (const float4*)(qg + ((size_t)(gi * WW + gj)) * HD);
        #pragma unroll
        for (int q = 0; q < 8; ++q) {
            float4 v = qp[q];
            rq[q] = make_float4(v.x * SCALE, v.y * SCALE, v.z * SCALE, v.w * SCALE);
        }
    }
    __syncthreads();

    float p[K2];
    float den = 0.f;
    #pragma unroll
    for (int di = 0; di < KER; ++di) {
        #pragma unroll
        for (int dj = 0; dj < KER; ++dj) {
            const int pos4 = ((li + di) * HALO_J + (lj + dj)) * 4;
            float d0 = 0.f, d1 = 0.f, d2 = 0.f, d3 = 0.f;
            #pragma unroll
            for (int q = 0; q < 8; ++q) {
                float4 kv = *(const float4*)(smemf + q * PLANE + pos4);
                d0 = fmaf(rq[q].x, kv.x, d0);
                d1 = fmaf(rq[q].y, kv.y, d1);
                d2 = fmaf(rq[q].z, kv.z, d2);
                d3 = fmaf(rq[q].w, kv.w, d3);
            }
            float e = __expf((d0 + d1) + (d2 + d3));
            p[di * KER + dj] = e;
            den += e;
        }
    }
    __syncthreads();

    #pragma unroll 1
    for (int idx = tid; idx < NF4; idx += 128) {
        int pos = idx >> 3, f = idx & 7;
        int r = pos / HALO_J, c = pos - r * HALO_J;
        int ri = i0 - PAD + r, rj = j0 - PAD + c;
        float4 vv = make_float4(0.f, 0.f, 0.f, 0.f);
        if (ri >= 0 && ri < HH && rj >= 0 && rj < WW)
            vv = *(const float4*)(vg + ((size_t)(ri * WW + rj)) * HD + f * 4);
        *(float4*)(smemf + f * PLANE + pos * 4) = vv;
    }
    __syncthreads();

    float4 acc[8];
    #pragma unroll
    for (int q = 0; q < 8; ++q) acc[q] = make_float4(0.f, 0.f, 0.f, 0.f);

    #pragma unroll
    for (int di = 0; di < KER; ++di) {
        #pragma unroll
        for (int dj = 0; dj < KER; ++dj) {
            const int pos4 = ((li + di) * HALO_J + (lj + dj)) * 4;
            const float pw = p[di * KER + dj];
            #pragma unroll
            for (int q = 0; q < 8; ++q) {
                float4 vv = *(const float4*)(smemf + q * PLANE + pos4);
                acc[q].x = fmaf(pw, vv.x, acc[q].x);
                acc[q].y = fmaf(pw, vv.y, acc[q].y);
                acc[q].z = fmaf(pw, vv.z, acc[q].z);
                acc[q].w = fmaf(pw, vv.w, acc[q].w);
            }
        }
    }

    const float inv = 1.f / den;
    float* op = g_attn + ((size_t)(b * TOK + gi * WW + gj)) * EMBED + h * HD;
    #pragma unroll
    for (int q = 0; q < 8; ++q) {
        float4 r = make_float4(acc[q].x * inv, acc[q].y * inv,
                               acc[q].z * inv, acc[q].w * inv);
        *(float4*)(op + q * 4) = r;
    }
}

// ---------------- launch -----------------------------------------------------
extern "C" void kernel_launch(void* const* d_in, const int* in_sizes, int n_in,
                              void* d_out, int out_size) {
    const float* x     = (const float*)d_in[0];
    const float* ctx   = (const float*)d_in[1];
    const float* Wqkv  = (const float*)d_in[2];
    const float* bqkv  = (const float*)d_in[3];
    const float* A     = (const float*)d_in[4];
    const float* Blora = (const float*)d_in[5];
    const float* Vlora = (const float*)d_in[6];
    const float* g1w   = (const float*)d_in[7];
    const float* g1b   = (const float*)d_in[8];
    const float* g2w   = (const float*)d_in[9];
    const float* g2b   = (const float*)d_in[10];
    const float* Wproj = (const float*)d_in[11];
    const float* bproj = (const float*)d_in[12];
    float* out = (float*)d_out;

    cudaFuncSetAttribute(attn_kernel,
                         cudaFuncAttributeMaxDynamicSharedMemorySize, ATTN_SMEM);
    cudaFuncSetAttribute(gemm_mma<true>,
                         cudaFuncAttributeMaxDynamicSharedMemorySize, GEMM_SMEM);
    cudaFuncSetAttribute(gemm_mma<false>,
                         cudaFuncAttributeMaxDynamicSharedMemorySize, GEMM_SMEM);

    prep_kernel<<<1, 128>>>(ctx, Blora, g1w, g1b, g2w, g2b);
    weff_kernel<<<768, 256>>>(Wqkv, A, Vlora);
    // qkv: M=4096 (32 tiles) x N=384 (3 tiles of 128) per batch
    gemm_mma<true><<<dim3(32, 3, 4), 256, GEMM_SMEM>>>(x, nullptr, bqkv, nullptr);
    attn_kernel<<<dim3(WW / TILE_J, HH / TILE_I, NB * NH), 128, ATTN_SMEM>>>();
    // proj: M=16384 (128 tiles) x N=128 (1 tile)
    gemm_mma<false><<<dim3(128, 1, 1), 256, GEMM_SMEM>>>(nullptr, Wproj, bproj, out);
}